// round 3
// baseline (speedup 1.0000x reference)
#include <cuda_runtime.h>
#include <cstdint>

// Problem constants
#define B_  8
#define C_  64
#define N_  4096
#define K_  20
#define M_  8
#define OC_ 64
#define CM_ 512   // C_*M_

// ---------------- scratch (no allocs allowed) ----------------
__device__ __align__(16) float g_featT[B_ * N_ * C_];   // [b][n][c]   8 MB
__device__ __align__(16) float g_xT[B_ * N_ * 4];       // [b][n][0..2], pad
__device__ __align__(16) float g_agg[(size_t)B_ * N_ * CM_]; // [point][c*8+m] 64 MB

// ---------------- kernel 1: transpose feature (B,C,N) -> (B,N,C) ----------------
__global__ void k_transpose_feat(const float* __restrict__ f) {
    __shared__ float tile[32][33];
    int b  = blockIdx.z;
    int c0 = blockIdx.y * 32;
    int n0 = blockIdx.x * 32;
    int tx = threadIdx.x, ty = threadIdx.y;      // 32 x 8
    const float* src = f + ((size_t)b * C_ + c0) * N_ + n0;
#pragma unroll
    for (int j = 0; j < 32; j += 8)
        tile[ty + j][tx] = src[(size_t)(ty + j) * N_ + tx];
    __syncthreads();
    float* dst = g_featT + ((size_t)b * N_ + n0) * C_ + c0;
#pragma unroll
    for (int j = 0; j < 32; j += 8)
        dst[(size_t)(ty + j) * C_ + tx] = tile[tx][ty + j];
}

// ---------------- kernel 2: transpose x (B,3,N) -> (B,N,4) ----------------
__global__ void k_transpose_x(const float* __restrict__ x) {
    int i = blockIdx.x * blockDim.x + threadIdx.x;   // 0..32767
    int b = i >> 12;
    int n = i & (N_ - 1);
    const float* xb = x + (size_t)b * 3 * N_;
    float4 v;
    v.x = xb[n];
    v.y = xb[N_ + n];
    v.z = xb[2 * N_ + n];
    v.w = 0.f;
    *reinterpret_cast<float4*>(g_xT + (size_t)i * 4) = v;
}

// ---------------- kernel 3: per-point P + softmax + agg ----------------
__global__ __launch_bounds__(128) void k_point(const int* __restrict__ neigh,
                                               const float* __restrict__ kern) {
    __shared__ int   sIdx[K_];
    __shared__ __align__(16) float sX[K_][4];
    __shared__ float sK[24];          // kernels[c][m], c<3, m<8
    __shared__ __align__(16) float sP[K_][M_];
    __shared__ __align__(16) float sF[K_][C_];

    int t = threadIdx.x;
    int point = blockIdx.x;
    int b = point >> 12;

    if (t < K_) sIdx[t] = neigh[(size_t)point * K_ + t] & (N_ - 1);
    if (t >= 64 && t < 88) sK[t - 64] = kern[t - 64];
    __syncthreads();

    if (t < K_) {
        *reinterpret_cast<float4*>(sX[t]) =
            *reinterpret_cast<const float4*>(g_xT + (size_t)((b << 12) + sIdx[t]) * 4);
    }
    // gather neighbor features: 20 rows x 64 floats, coalesced 256B rows
    float* sFlin = &sF[0][0];
#pragma unroll
    for (int i = t; i < K_ * C_; i += 128) {
        int k = i >> 6, c = i & 63;
        sFlin[i] = g_featT[(((size_t)(b << 12) + sIdx[k]) << 6) + c];
    }
    __syncthreads();

    // P[k][m] = sum_c (x[k][c]-x[0][c]) * kern[c][m]  (+1 at [0][0])
    // K_*M_ = 160 entries > 128 threads -> strided loop (2 entries for t < 32)
    for (int i = t; i < K_ * M_; i += 128) {
        int k = i >> 3, m = i & 7;
        float p = (sX[k][0] - sX[0][0]) * sK[m]
                + (sX[k][1] - sX[0][1]) * sK[8 + m]
                + (sX[k][2] - sX[0][2]) * sK[16 + m];
        if (i == 0) p += 1.0f;
        sP[k][m] = p;
    }
    __syncthreads();

    // softmax over k, per column m (8 threads)
    if (t < M_) {
        float mx = -1e30f;
#pragma unroll
        for (int k = 0; k < K_; k++) mx = fmaxf(mx, sP[k][t]);
        float e[K_];
        float s = 0.f;
#pragma unroll
        for (int k = 0; k < K_; k++) { e[k] = __expf(sP[k][t] - mx); s += e[k]; }
        float inv = 1.f / s;
#pragma unroll
        for (int k = 0; k < K_; k++) sP[k][t] = e[k] * inv;
    }
    __syncthreads();

    // agg[c][m] = sum_k sF[k][c] * P[k][m]; thread t -> c = t>>1, m-half = (t&1)*4
    int c  = t >> 1;
    int mh = (t & 1) * 4;
    float4 acc = make_float4(0.f, 0.f, 0.f, 0.f);
#pragma unroll
    for (int k = 0; k < K_; k++) {
        float f = sF[k][c];
        float4 p4 = *reinterpret_cast<const float4*>(&sP[k][mh]);
        acc.x = fmaf(f, p4.x, acc.x);
        acc.y = fmaf(f, p4.y, acc.y);
        acc.z = fmaf(f, p4.z, acc.z);
        acc.w = fmaf(f, p4.w, acc.w);
    }
    // offset c*8 + mh == t*4 -> fully coalesced float4 stores
    *reinterpret_cast<float4*>(g_agg + (size_t)point * CM_ + t * 4) = acc;
}

// ---------------- kernel 4: out = leakyrelu(agg @ W^T + b) + feature ----------------
// Tile: 128 points x 64 oc, K=512 in chunks of 32. 128 threads, 8x8 thread tile.
// Packed fp32x2 FMAs (2 points per instruction) for 2x FFMA throughput.
__global__ __launch_bounds__(128) void k_conv(const float* __restrict__ W,
                                              const float* __restrict__ bias,
                                              const float* __restrict__ feature,
                                              float* __restrict__ out) {
    __shared__ __align__(16) float  As[32][130]; // [k][p], even pad keeps 8B align
    __shared__ __align__(16) float2 Wd[32][64];  // W duplicated into both packed lanes

    int t = threadIdx.x;
    int pt0 = blockIdx.x * 128;
    const float* gA = g_agg + (size_t)pt0 * CM_;

    unsigned long long acc[4][8];
#pragma unroll
    for (int i = 0; i < 4; i++)
#pragma unroll
        for (int j = 0; j < 8; j++) acc[i][j] = 0ull;

    int p0  = (t >> 3) * 8;   // point sub-tile
    int oc0 = (t & 7) * 8;    // oc sub-tile

    for (int kc = 0; kc < CM_; kc += 32) {
        // stage A chunk (transposed)
#pragma unroll
        for (int j = 0; j < 8; j++) {
            int q = t + j * 128;
            int p = q >> 3, kq = (q & 7) * 4;
            float4 v = *reinterpret_cast<const float4*>(gA + (size_t)p * CM_ + kc + kq);
            As[kq + 0][p] = v.x; As[kq + 1][p] = v.y;
            As[kq + 2][p] = v.z; As[kq + 3][p] = v.w;
        }
        // stage W chunk (transposed + lane-duplicated)
#pragma unroll
        for (int j = 0; j < 4; j++) {
            int q = t + j * 128;
            int oc = q >> 3, kq = (q & 7) * 4;
            float4 v = *reinterpret_cast<const float4*>(W + (size_t)oc * CM_ + kc + kq);
            Wd[kq + 0][oc] = make_float2(v.x, v.x);
            Wd[kq + 1][oc] = make_float2(v.y, v.y);
            Wd[kq + 2][oc] = make_float2(v.z, v.z);
            Wd[kq + 3][oc] = make_float2(v.w, v.w);
        }
        __syncthreads();

#pragma unroll 4
        for (int k = 0; k < 32; k++) {
            unsigned long long a[4], w[8];
            const unsigned long long* ap =
                reinterpret_cast<const unsigned long long*>(&As[k][p0]);
#pragma unroll
            for (int i = 0; i < 4; i++) a[i] = ap[i];
            const unsigned long long* wp =
                reinterpret_cast<const unsigned long long*>(&Wd[k][oc0]);
#pragma unroll
            for (int j = 0; j < 8; j++) w[j] = wp[j];
#pragma unroll
            for (int i = 0; i < 4; i++)
#pragma unroll
                for (int j = 0; j < 8; j++)
                    asm("fma.rn.f32x2 %0, %1, %2, %0;"
                        : "+l"(acc[i][j]) : "l"(a[i]), "l"(w[j]));
        }
        __syncthreads();
    }

    // epilogue: bias + leaky relu + residual, write (B, OC, N) layout
    int pt = pt0 + p0;
    int b  = pt >> 12;
    int n  = pt & (N_ - 1);
#pragma unroll
    for (int j = 0; j < 8; j++) {
        int oc = oc0 + j;
        float bv = bias[oc];
        const float* frow = feature + (((size_t)b * OC_ + oc) << 12) + n;
        float*       orow = out     + (((size_t)b * OC_ + oc) << 12) + n;
#pragma unroll
        for (int i = 0; i < 4; i++) {
            float2 v = *reinterpret_cast<float2*>(&acc[i][j]);
            float r0 = v.x + bv;
            float r1 = v.y + bv;
            r0 = r0 > 0.f ? r0 : 0.2f * r0;
            r1 = r1 > 0.f ? r1 : 0.2f * r1;
            float2 fr = *reinterpret_cast<const float2*>(frow + 2 * i);
            float2 o;
            o.x = r0 + fr.x;
            o.y = r1 + fr.y;
            *reinterpret_cast<float2*>(orow + 2 * i) = o;
        }
    }
}

// ---------------- launch ----------------
extern "C" void kernel_launch(void* const* d_in, const int* in_sizes, int n_in,
                              void* d_out, int out_size) {
    const float* x      = (const float*)d_in[0];
    const float* feat   = (const float*)d_in[1];
    const int*   neigh  = (const int*)d_in[2];    // int32: JAX x64-disabled downcast
    const float* kern   = (const float*)d_in[3];
    const float* conv_w = (const float*)d_in[4];
    const float* conv_b = (const float*)d_in[5];
    float*       out    = (float*)d_out;

    k_transpose_feat<<<dim3(N_ / 32, C_ / 32, B_), dim3(32, 8)>>>(feat);
    k_transpose_x<<<(B_ * N_) / 256, 256>>>(x);
    k_point<<<B_ * N_, 128>>>(neigh, kern);
    k_conv<<<(B_ * N_) / 128, 128>>>(conv_w, conv_b, feat, out);
}

// round 4
// speedup vs baseline: 2.6380x; 2.6380x over previous
#include <cuda_runtime.h>
#include <cstdint>

// Problem constants
#define B_  8
#define C_  64
#define N_  4096
#define K_  20
#define M_  8
#define OC_ 64
#define CM_ 512   // C_*M_

// ---------------- scratch (no allocs allowed) ----------------
__device__ __align__(16) float g_featT[B_ * N_ * C_];        // [b][n][c] 8 MB
__device__ __align__(16) float g_xT[B_ * N_ * 4];            // [b][n][xyz0]
__device__ __align__(16) float g_agg[(size_t)B_ * N_ * CM_]; // [point][c*8+m], tf32-rounded
__device__ __align__(16) float g_Wc[OC_ * CM_];              // conv_w, tf32-rounded

__device__ __forceinline__ float to_tf32(float x) {
    float r;
    asm("cvt.rna.tf32.f32 %0, %1;" : "=f"(r) : "f"(x));
    return r;
}

__device__ __forceinline__ void cp_async16(void* dst, const void* src) {
    uint32_t d = (uint32_t)__cvta_generic_to_shared(dst);
    asm volatile("cp.async.cg.shared.global [%0], [%1], 16;" :: "r"(d), "l"(src));
}

__device__ __forceinline__ void mma_tf32(float* c, const uint32_t* a, const uint32_t* b) {
    asm volatile(
        "mma.sync.aligned.m16n8k8.row.col.f32.tf32.tf32.f32 "
        "{%0,%1,%2,%3}, {%4,%5,%6,%7}, {%8,%9}, {%0,%1,%2,%3};"
        : "+f"(c[0]), "+f"(c[1]), "+f"(c[2]), "+f"(c[3])
        : "r"(a[0]), "r"(a[1]), "r"(a[2]), "r"(a[3]), "r"(b[0]), "r"(b[1]));
}

// ---------------- kernel 1: transpose feature (B,C,N) -> (B,N,C) ----------------
__global__ void k_transpose_feat(const float* __restrict__ f) {
    __shared__ float tile[32][33];
    int b  = blockIdx.z;
    int c0 = blockIdx.y * 32;
    int n0 = blockIdx.x * 32;
    int tx = threadIdx.x, ty = threadIdx.y;      // 32 x 8
    const float* src = f + ((size_t)b * C_ + c0) * N_ + n0;
#pragma unroll
    for (int j = 0; j < 32; j += 8)
        tile[ty + j][tx] = src[(size_t)(ty + j) * N_ + tx];
    __syncthreads();
    float* dst = g_featT + ((size_t)b * N_ + n0) * C_ + c0;
#pragma unroll
    for (int j = 0; j < 32; j += 8)
        dst[(size_t)(ty + j) * C_ + tx] = tile[tx][ty + j];
}

// ---------------- kernel 2: transpose x (B,3,N) -> (B,N,4) ----------------
__global__ void k_transpose_x(const float* __restrict__ x) {
    int i = blockIdx.x * blockDim.x + threadIdx.x;   // 0..32767
    int b = i >> 12;
    int n = i & (N_ - 1);
    const float* xb = x + (size_t)b * 3 * N_;
    float4 v;
    v.x = xb[n];
    v.y = xb[N_ + n];
    v.z = xb[2 * N_ + n];
    v.w = 0.f;
    *reinterpret_cast<float4*>(g_xT + (size_t)i * 4) = v;
}

// ---------------- kernel 2b: round conv_w to tf32 once ----------------
__global__ void k_prep_w(const float* __restrict__ W) {
    int i = blockIdx.x * blockDim.x + threadIdx.x;
    if (i < OC_ * CM_) g_Wc[i] = to_tf32(W[i]);
}

// ---------------- kernel 3: per-point P + softmax + agg ----------------
__global__ __launch_bounds__(128) void k_point(const int* __restrict__ neigh,
                                               const float* __restrict__ kern) {
    __shared__ int   sIdx[K_];
    __shared__ __align__(16) float sX[K_][4];
    __shared__ float sK[24];
    __shared__ __align__(16) float sP[K_][M_];
    __shared__ __align__(16) float sF[K_][C_];

    int t = threadIdx.x;
    int point = blockIdx.x;
    int b = point >> 12;

    if (t < K_) sIdx[t] = neigh[(size_t)point * K_ + t] & (N_ - 1);
    if (t >= 64 && t < 88) sK[t - 64] = kern[t - 64];
    __syncthreads();

    if (t < K_) {
        *reinterpret_cast<float4*>(sX[t]) =
            *reinterpret_cast<const float4*>(g_xT + (size_t)((b << 12) + sIdx[t]) * 4);
    }
    // gather neighbor features as float4: 20 rows x 16 float4
    float4* sF4 = reinterpret_cast<float4*>(&sF[0][0]);
#pragma unroll
    for (int i = t; i < K_ * 16; i += 128) {
        int k = i >> 4, c4 = i & 15;
        sF4[i] = *reinterpret_cast<const float4*>(
            g_featT + ((((size_t)(b << 12) + sIdx[k]) << 6) + c4 * 4));
    }
    __syncthreads();

    // P[k][m] (K_*M_ = 160 > 128 threads -> strided)
    for (int i = t; i < K_ * M_; i += 128) {
        int k = i >> 3, m = i & 7;
        float p = (sX[k][0] - sX[0][0]) * sK[m]
                + (sX[k][1] - sX[0][1]) * sK[8 + m]
                + (sX[k][2] - sX[0][2]) * sK[16 + m];
        if (i == 0) p += 1.0f;
        sP[k][m] = p;
    }
    __syncthreads();

    // softmax over k per column m
    if (t < M_) {
        float mx = -1e30f;
#pragma unroll
        for (int k = 0; k < K_; k++) mx = fmaxf(mx, sP[k][t]);
        float e[K_];
        float s = 0.f;
#pragma unroll
        for (int k = 0; k < K_; k++) { e[k] = __expf(sP[k][t] - mx); s += e[k]; }
        float inv = 1.f / s;
#pragma unroll
        for (int k = 0; k < K_; k++) sP[k][t] = e[k] * inv;
    }
    __syncthreads();

    // agg[c][m] = sum_k sF[k][c]*P[k][m]; thread -> c=t>>1, m-half=(t&1)*4
    int c  = t >> 1;
    int mh = (t & 1) * 4;
    float4 acc = make_float4(0.f, 0.f, 0.f, 0.f);
#pragma unroll
    for (int k = 0; k < K_; k++) {
        float f = sF[k][c];
        float4 p4 = *reinterpret_cast<const float4*>(&sP[k][mh]);
        acc.x = fmaf(f, p4.x, acc.x);
        acc.y = fmaf(f, p4.y, acc.y);
        acc.z = fmaf(f, p4.z, acc.z);
        acc.w = fmaf(f, p4.w, acc.w);
    }
    // round to tf32 for the tensor-core GEMM
    acc.x = to_tf32(acc.x); acc.y = to_tf32(acc.y);
    acc.z = to_tf32(acc.z); acc.w = to_tf32(acc.w);
    *reinterpret_cast<float4*>(g_agg + (size_t)point * CM_ + t * 4) = acc;
}

// ---------------- kernel 4: tf32 tensor-core GEMM + fused epilogue ----------------
// Tile: 64 points x 64 oc, 512 blocks, 128 threads (4 warps).
// Warp w: m16 row band [w*16, w*16+16) x all 64 oc. K chunks of 32, cp.async dbl-buf.
#define KC_ 32
__global__ __launch_bounds__(128) void k_conv(const float* __restrict__ bias,
                                              const float* __restrict__ feature,
                                              float* __restrict__ out) {
    __shared__ __align__(16) float As[2][64][36];   // [stage][pt][k] pad->36
    __shared__ __align__(16) float Ws[2][64][36];   // [stage][oc][k]

    int t    = threadIdx.x;
    int warp = t >> 5;
    int lane = t & 31;
    int g    = lane >> 2;    // groupID
    int tig  = lane & 3;     // thread in group
    int pt0  = blockIdx.x * 64;
    int pm   = warp * 16;

    const float* gA = g_agg + (size_t)pt0 * CM_;

    float acc[8][4];
#pragma unroll
    for (int nt = 0; nt < 8; nt++)
#pragma unroll
        for (int i = 0; i < 4; i++) acc[nt][i] = 0.f;

    int row = t >> 3;            // 0..15 per pass group of 8 lanes
    int c4  = (t & 7) * 4;

    // issue chunk 0
    {
        const int kc = 0;
#pragma unroll
        for (int j = 0; j < 4; j++) {
            int r = row + j * 16;
            cp_async16(&As[0][r][c4], gA + (size_t)r * CM_ + kc + c4);
            cp_async16(&Ws[0][r][c4], g_Wc + (size_t)r * CM_ + kc + c4);
        }
        asm volatile("cp.async.commit_group;");
    }

    for (int ch = 0; ch < CM_ / KC_; ch++) {
        int s = ch & 1;
        if (ch < CM_ / KC_ - 1) {
            int kc = (ch + 1) * KC_;
            int sn = s ^ 1;
#pragma unroll
            for (int j = 0; j < 4; j++) {
                int r = row + j * 16;
                cp_async16(&As[sn][r][c4], gA + (size_t)r * CM_ + kc + c4);
                cp_async16(&Ws[sn][r][c4], g_Wc + (size_t)r * CM_ + kc + c4);
            }
            asm volatile("cp.async.commit_group;");
            asm volatile("cp.async.wait_group 1;");
        } else {
            asm volatile("cp.async.wait_group 0;");
        }
        __syncthreads();

#pragma unroll
        for (int ks = 0; ks < KC_; ks += 8) {
            uint32_t a[4];
            a[0] = *reinterpret_cast<const uint32_t*>(&As[s][pm + g][ks + tig]);
            a[1] = *reinterpret_cast<const uint32_t*>(&As[s][pm + g + 8][ks + tig]);
            a[2] = *reinterpret_cast<const uint32_t*>(&As[s][pm + g][ks + tig + 4]);
            a[3] = *reinterpret_cast<const uint32_t*>(&As[s][pm + g + 8][ks + tig + 4]);
#pragma unroll
            for (int nt = 0; nt < 8; nt++) {
                uint32_t b[2];
                b[0] = *reinterpret_cast<const uint32_t*>(&Ws[s][nt * 8 + g][ks + tig]);
                b[1] = *reinterpret_cast<const uint32_t*>(&Ws[s][nt * 8 + g][ks + tig + 4]);
                mma_tf32(acc[nt], a, b);
            }
        }
        __syncthreads();
    }

    // epilogue: bias + leakyrelu -> smem tile o[oc][n], then coalesced residual+store
    float* Os = &As[0][0][0];   // 64 x 68 floats fits in As
#pragma unroll
    for (int nt = 0; nt < 8; nt++) {
        int oc = nt * 8 + tig * 2;
        float b0 = bias[oc], b1 = bias[oc + 1];
        int r0 = pm + g, r1 = pm + g + 8;
        float v0 = acc[nt][0] + b0;
        float v1 = acc[nt][1] + b1;
        float v2 = acc[nt][2] + b0;
        float v3 = acc[nt][3] + b1;
        v0 = v0 > 0.f ? v0 : 0.2f * v0;
        v1 = v1 > 0.f ? v1 : 0.2f * v1;
        v2 = v2 > 0.f ? v2 : 0.2f * v2;
        v3 = v3 > 0.f ? v3 : 0.2f * v3;
        Os[oc * 68 + r0]       = v0;
        Os[(oc + 1) * 68 + r0] = v1;
        Os[oc * 68 + r1]       = v2;
        Os[(oc + 1) * 68 + r1] = v3;
    }
    __syncthreads();

    int b  = pt0 >> 12;
    int n0 = pt0 & (N_ - 1);
#pragma unroll
    for (int j = 0; j < 8; j++) {
        int q  = t + j * 128;          // 1024 float4 total
        int oc = q >> 4;
        int n4 = (q & 15) * 4;
        float4 v = *reinterpret_cast<const float4*>(Os + oc * 68 + n4);
        size_t off = (((size_t)b * OC_ + oc) << 12) + n0 + n4;
        float4 fr = *reinterpret_cast<const float4*>(feature + off);
        v.x += fr.x; v.y += fr.y; v.z += fr.z; v.w += fr.w;
        *reinterpret_cast<float4*>(out + off) = v;
    }
}

// ---------------- launch ----------------
extern "C" void kernel_launch(void* const* d_in, const int* in_sizes, int n_in,
                              void* d_out, int out_size) {
    const float* x      = (const float*)d_in[0];
    const float* feat   = (const float*)d_in[1];
    const int*   neigh  = (const int*)d_in[2];    // int32 (JAX x64-disabled)
    const float* kern   = (const float*)d_in[3];
    const float* conv_w = (const float*)d_in[4];
    const float* conv_b = (const float*)d_in[5];
    float*       out    = (float*)d_out;

    k_transpose_feat<<<dim3(N_ / 32, C_ / 32, B_), dim3(32, 8)>>>(feat);
    k_transpose_x<<<(B_ * N_) / 256, 256>>>(x);
    k_prep_w<<<(OC_ * CM_ + 255) / 256, 256>>>(conv_w);
    k_point<<<B_ * N_, 128>>>(neigh, kern);
    k_conv<<<(B_ * N_) / 64, 128>>>(conv_b, feat, out);
}